// round 1
// baseline (speedup 1.0000x reference)
#include <cuda_runtime.h>
#include <math.h>

constexpr int IMH = 256, IMW = 256;
constexpr int HWSZ = IMH * IMW;       // 65536
constexpr int BB = 2;

// ---------------- scratch (device globals; no runtime allocation) ----------------
__device__ float g_qkin  [(size_t)BB * 100 * HWSZ];
__device__ float g_qureys[(size_t)BB *  96 * HWSZ];
__device__ float g_value [(size_t)BB *  96 * HWSZ];
__device__ float g_val   [(size_t)BB *  96 * HWSZ];
__device__ float g_off   [(size_t)BB *  96 * HWSZ];
__device__ float g_aw    [(size_t)BB *  48 * HWSZ];
__device__ float g_attn  [(size_t)BB *  32 * HWSZ];
__device__ float g_out1  [(size_t)BB *  32 * HWSZ];
__device__ float g_out2  [(size_t)BB *  32 * HWSZ];
__device__ float g_tseq  [(size_t)BB *  64 * HWSZ];
__device__ float g_ff1   [(size_t)BB *  32 * HWSZ];
__device__ float g_out3  [(size_t)BB *  32 * HWSZ];

__device__ __forceinline__ float lrelu(float v) { return v >= 0.f ? v : 0.1f * v; }

// ---------------- kernel 1: build qk_in (flow warps + concat) ----------------
__device__ __forceinline__ void sample32(const float* __restrict__ img, float sx, float sy,
                                         float* __restrict__ dst, int q)
{
    float x0f = floorf(sx), y0f = floorf(sy);
    float lx = sx - x0f, ly = sy - y0f;
    int x0 = (int)x0f, y0 = (int)y0f;
    float w00 = (1.f - lx) * (1.f - ly);
    float w01 = lx * (1.f - ly);
    float w10 = (1.f - lx) * ly;
    float w11 = lx * ly;
    bool vx0 = (unsigned)x0       < (unsigned)IMW;
    bool vx1 = (unsigned)(x0 + 1) < (unsigned)IMW;
    bool vy0 = (unsigned)y0       < (unsigned)IMH;
    bool vy1 = (unsigned)(y0 + 1) < (unsigned)IMH;
    int cx0 = min(max(x0, 0), IMW - 1), cx1 = min(max(x0 + 1, 0), IMW - 1);
    int cy0 = min(max(y0, 0), IMH - 1), cy1 = min(max(y0 + 1, 0), IMH - 1);
    int i00 = cy0 * IMW + cx0, i01 = cy0 * IMW + cx1;
    int i10 = cy1 * IMW + cx0, i11 = cy1 * IMW + cx1;
    float m00 = (vx0 && vy0) ? w00 : 0.f;
    float m01 = (vx1 && vy0) ? w01 : 0.f;
    float m10 = (vx0 && vy1) ? w10 : 0.f;
    float m11 = (vx1 && vy1) ? w11 : 0.f;
    #pragma unroll 4
    for (int c = 0; c < 32; ++c) {
        const float* p = img + (size_t)c * HWSZ;
        dst[(size_t)c * HWSZ + q] = m00 * p[i00] + m01 * p[i01] + m10 * p[i10] + m11 * p[i11];
    }
}

__global__ void build_qkin_kernel(const float* __restrict__ frame,
                                  const float* __restrict__ flow_f,
                                  const float* __restrict__ flow_b,
                                  float* __restrict__ qkin)
{
    int id = blockIdx.x * blockDim.x + threadIdx.x;
    if (id >= BB * HWSZ) return;
    int b = id / HWSZ, q = id % HWSZ;
    int px = q & (IMW - 1), py = q >> 8;

    // flow_backward shape (B, 2, 2, H, W); [:,0]
    const float* fb = flow_b + (size_t)b * 2 * 2 * HWSZ;
    float fbx = fb[q], fby = fb[HWSZ + q];
    // flow_forward [:,1]
    const float* ff = flow_f + (size_t)b * 2 * 2 * HWSZ + (size_t)2 * HWSZ;
    float ffx = ff[q], ffy = ff[HWSZ + q];

    float* dst = qkin + (size_t)b * 100 * HWSZ;
    // warp01 = warp(frame[:,0], flow_backward[:,0])
    sample32(frame + ((size_t)b * 3 + 0) * 32 * HWSZ, (float)px + fbx, (float)py + fby, dst, q);
    // frame[:,1]
    const float* f1 = frame + ((size_t)b * 3 + 1) * 32 * HWSZ;
    #pragma unroll 4
    for (int c = 0; c < 32; ++c)
        dst[(size_t)(32 + c) * HWSZ + q] = f1[(size_t)c * HWSZ + q];
    // warp21 = warp(frame[:,2], flow_forward[:,1])
    sample32(frame + ((size_t)b * 3 + 2) * 32 * HWSZ, (float)px + ffx, (float)py + ffy,
             dst + (size_t)64 * HWSZ, q);
    dst[(size_t)96 * HWSZ + q] = ffx;
    dst[(size_t)97 * HWSZ + q] = ffy;
    dst[(size_t)98 * HWSZ + q] = fbx;
    dst[(size_t)99 * HWSZ + q] = fby;
}

// ---------------- generic tiled 3x3 conv ----------------
// tile: 32(x) x 16(y) output pixels, 16 out channels per block,
// each thread: 2 pixels x 16 oc accumulators. CIN must be a multiple of 4.
template<int DIL, int ACT, bool RES>
__global__ void __launch_bounds__(256) conv3x3_kernel(
    const float* __restrict__ in, const float* __restrict__ Wt,
    const float* __restrict__ bias, const float* __restrict__ res, size_t resStride,
    float* __restrict__ out, int CIN, int COUT)
{
    constexpr int TX = 32, TY = 16, OCB = 16;
    constexpr int IW = TX + 2 * DIL, IH = TY + 2 * DIL;
    __shared__ float s_in[4][IH][IW];
    __shared__ __align__(16) float s_w[4][9][OCB];

    const int tid = threadIdx.x;
    const int px = tid & 31, py = tid >> 5;          // px 0..31, py 0..7
    const int x0 = blockIdx.x * TX, y0 = blockIdx.y * TY;
    const int ngrp = COUT >> 4;
    const int img = blockIdx.z / ngrp;
    const int ocBase = (blockIdx.z % ngrp) * OCB;

    const float* inImg = in + (size_t)img * CIN * HWSZ;

    float accA[OCB], accB[OCB];
    #pragma unroll
    for (int i = 0; i < OCB; ++i) { accA[i] = 0.f; accB[i] = 0.f; }

    const int nch = CIN >> 2;
    for (int cc = 0; cc < nch; ++cc) {
        const int ciBase = cc * 4;
        // load input tile (4 channels, with halo, zero padded)
        for (int idx = tid; idx < 4 * IH * IW; idx += 256) {
            int ci = idx / (IH * IW);
            int rem = idx % (IH * IW);
            int ly = rem / IW, lx = rem % IW;
            int gy = y0 - DIL + ly, gx = x0 - DIL + lx;
            float v = 0.f;
            if ((unsigned)gy < (unsigned)IMH && (unsigned)gx < (unsigned)IMW)
                v = inImg[(size_t)(ciBase + ci) * HWSZ + gy * IMW + gx];
            s_in[ci][ly][lx] = v;
        }
        // load weights: s_w[ci][k][oc]
        for (int idx = tid; idx < 4 * 9 * OCB; idx += 256) {
            int oc = idx & 15;
            int k  = (idx >> 4) % 9;
            int ci = idx / (9 * OCB);
            s_w[ci][k][oc] = Wt[((size_t)(ocBase + oc) * CIN + ciBase + ci) * 9 + k];
        }
        __syncthreads();

        #pragma unroll
        for (int ci = 0; ci < 4; ++ci) {
            #pragma unroll
            for (int k = 0; k < 9; ++k) {
                const int ky = k / 3, kx = k % 3;
                float xa = s_in[ci][py +     ky * DIL][px + kx * DIL];
                float xb = s_in[ci][py + 8 + ky * DIL][px + kx * DIL];
                const float4* wp = reinterpret_cast<const float4*>(&s_w[ci][k][0]);
                #pragma unroll
                for (int o4 = 0; o4 < 4; ++o4) {
                    float4 w = wp[o4];
                    accA[o4 * 4 + 0] += xa * w.x;  accB[o4 * 4 + 0] += xb * w.x;
                    accA[o4 * 4 + 1] += xa * w.y;  accB[o4 * 4 + 1] += xb * w.y;
                    accA[o4 * 4 + 2] += xa * w.z;  accB[o4 * 4 + 2] += xb * w.z;
                    accA[o4 * 4 + 3] += xa * w.w;  accB[o4 * 4 + 3] += xb * w.w;
                }
            }
        }
        __syncthreads();
    }

    const int ox = x0 + px;
    const int oyA = y0 + py, oyB = y0 + py + 8;
    const size_t outImg = (size_t)img * COUT * HWSZ;
    #pragma unroll
    for (int oc = 0; oc < OCB; ++oc) {
        float bv = bias[ocBase + oc];
        float vA = accA[oc] + bv;
        float vB = accB[oc] + bv;
        if (RES) {
            const float* rp = res + (size_t)img * resStride + (size_t)(ocBase + oc) * HWSZ;
            vA += rp[oyA * IMW + ox];
            vB += rp[oyB * IMW + ox];
        }
        if (ACT) { vA = lrelu(vA); vB = lrelu(vB); }
        size_t chOff = outImg + (size_t)(ocBase + oc) * HWSZ;
        out[chOff + oyA * IMW + ox] = vA;
        out[chOff + oyB * IMW + ox] = vB;
    }
}

// ---------------- deformable attention ----------------
// val: (b, t=3, c=32, HW) ; off: (b, 96, HW) ; aw: (b, 48, HW) logits
// out: (b, 32, HW) with channel = head*8 + e
__global__ void deform_attn_kernel(const float* __restrict__ val,
                                   const float* __restrict__ off,
                                   const float* __restrict__ awl,
                                   float* __restrict__ out)
{
    int id = blockIdx.x * blockDim.x + threadIdx.x;
    if (id >= BB * 4 * HWSZ) return;
    int q = id % HWSZ;
    int head = (id / HWSZ) & 3;
    int b = id / (4 * HWSZ);
    int px = q & (IMW - 1), py = q >> 8;

    // softmax over 12 logits
    const float* awp = awl + ((size_t)b * 48 + head * 12) * HWSZ + q;
    float lg[12];
    float mx = -1e30f;
    #pragma unroll
    for (int i = 0; i < 12; ++i) { lg[i] = awp[(size_t)i * HWSZ]; mx = fmaxf(mx, lg[i]); }
    float s = 0.f;
    #pragma unroll
    for (int i = 0; i < 12; ++i) { lg[i] = expf(lg[i] - mx); s += lg[i]; }
    float inv = 1.f / s;

    float acc[8];
    #pragma unroll
    for (int e = 0; e < 8; ++e) acc[e] = 0.f;

    const float* offp = off + ((size_t)b * 96 + head * 24) * HWSZ + q;

    for (int l = 0; l < 3; ++l) {
        const float* vbase = val + (((size_t)b * 3 + l) * 32 + head * 8) * HWSZ;
        #pragma unroll
        for (int p = 0; p < 4; ++p) {
            int ch = (l * 4 + p) * 2;
            float sx = (float)px + offp[(size_t)ch * HWSZ];
            float sy = (float)py + offp[(size_t)(ch + 1) * HWSZ];
            float a = lg[l * 4 + p] * inv;

            float x0f = floorf(sx), y0f = floorf(sy);
            float lx = sx - x0f, ly = sy - y0f;
            int x0 = (int)x0f, y0 = (int)y0f;
            float w00 = (1.f - lx) * (1.f - ly);
            float w01 = lx * (1.f - ly);
            float w10 = (1.f - lx) * ly;
            float w11 = lx * ly;
            bool vx0 = (unsigned)x0       < (unsigned)IMW;
            bool vx1 = (unsigned)(x0 + 1) < (unsigned)IMW;
            bool vy0 = (unsigned)y0       < (unsigned)IMH;
            bool vy1 = (unsigned)(y0 + 1) < (unsigned)IMH;
            int cx0 = min(max(x0, 0), IMW - 1), cx1 = min(max(x0 + 1, 0), IMW - 1);
            int cy0 = min(max(y0, 0), IMH - 1), cy1 = min(max(y0 + 1, 0), IMH - 1);
            float c00 = (vx0 && vy0) ? a * w00 : 0.f;
            float c01 = (vx1 && vy0) ? a * w01 : 0.f;
            float c10 = (vx0 && vy1) ? a * w10 : 0.f;
            float c11 = (vx1 && vy1) ? a * w11 : 0.f;
            int i00 = cy0 * IMW + cx0, i01 = cy0 * IMW + cx1;
            int i10 = cy1 * IMW + cx0, i11 = cy1 * IMW + cx1;
            #pragma unroll
            for (int e = 0; e < 8; ++e) {
                const float* vp = vbase + (size_t)e * HWSZ;
                acc[e] += c00 * vp[i00] + c01 * vp[i01] + c10 * vp[i10] + c11 * vp[i11];
            }
        }
    }

    float* op = out + ((size_t)b * 32 + head * 8) * HWSZ + q;
    #pragma unroll
    for (int e = 0; e < 8; ++e) op[(size_t)e * HWSZ] = acc[e];
}

// ---------------- concat [out2, srcframe[:,1]] ----------------
__global__ void build_tseq_kernel(const float* __restrict__ out2,
                                  const float* __restrict__ srcframe,
                                  float* __restrict__ tseq)
{
    int id = blockIdx.x * blockDim.x + threadIdx.x;
    if (id >= BB * 64 * HWSZ) return;
    int q = id % HWSZ;
    int c = (id / HWSZ) & 63;
    int b = id / (64 * HWSZ);
    float v;
    if (c < 32) v = out2[((size_t)b * 32 + c) * HWSZ + q];
    else        v = srcframe[(((size_t)b * 3 + 1) * 32 + (c - 32)) * HWSZ + q];
    tseq[((size_t)b * 64 + c) * HWSZ + q] = v;
}

// ---------------- final 1x1 conv + lrelu ----------------
__global__ void conv1x1_lrelu_kernel(const float* __restrict__ in,
                                     const float* __restrict__ Wt,
                                     const float* __restrict__ bias,
                                     float* __restrict__ out)
{
    __shared__ float s_w[32][32];
    __shared__ float s_b[32];
    int tid = threadIdx.x;
    for (int idx = tid; idx < 32 * 32; idx += 256)
        s_w[idx >> 5][idx & 31] = Wt[idx];
    if (tid < 32) s_b[tid] = bias[tid];
    __syncthreads();

    int id = blockIdx.x * 256 + tid;
    if (id >= BB * HWSZ) return;
    int b = id / HWSZ, q = id % HWSZ;

    float x[32];
    #pragma unroll
    for (int ci = 0; ci < 32; ++ci)
        x[ci] = in[((size_t)b * 32 + ci) * HWSZ + q];

    #pragma unroll 4
    for (int oc = 0; oc < 32; ++oc) {
        float s = s_b[oc];
        #pragma unroll
        for (int ci = 0; ci < 32; ++ci)
            s += x[ci] * s_w[oc][ci];
        out[((size_t)b * 32 + oc) * HWSZ + q] = lrelu(s);
    }
}

// ---------------- host launcher ----------------
extern "C" void kernel_launch(void* const* d_in, const int* in_sizes, int n_in,
                              void* d_out, int out_size)
{
    const float* frame   = (const float*)d_in[0];
    const float* srcfr   = (const float*)d_in[1];
    const float* flow_f  = (const float*)d_in[2];
    const float* flow_b  = (const float*)d_in[3];
    const float* W_qk = (const float*)d_in[4];   const float* b_qk = (const float*)d_in[5];
    const float* W_v  = (const float*)d_in[6];   const float* b_v  = (const float*)d_in[7];
    const float* W_vp = (const float*)d_in[8];   const float* b_vp = (const float*)d_in[9];
    const float* W_off= (const float*)d_in[10];  const float* b_off= (const float*)d_in[11];
    const float* W_aw = (const float*)d_in[12];  const float* b_aw = (const float*)d_in[13];
    const float* W_out= (const float*)d_in[14];  const float* b_out= (const float*)d_in[15];
    const float* W_ffd= (const float*)d_in[16];  const float* b_ffd= (const float*)d_in[17];
    const float* W_ff1= (const float*)d_in[18];  const float* b_ff1= (const float*)d_in[19];
    const float* W_ff2= (const float*)d_in[20];  const float* b_ff2= (const float*)d_in[21];
    const float* W_fu = (const float*)d_in[22];  const float* b_fu = (const float*)d_in[23];

    float *qkin, *qureys, *value, *val, *off, *aw, *attn, *out1, *out2, *tseq, *ff1, *out3;
    cudaGetSymbolAddress((void**)&qkin,   g_qkin);
    cudaGetSymbolAddress((void**)&qureys, g_qureys);
    cudaGetSymbolAddress((void**)&value,  g_value);
    cudaGetSymbolAddress((void**)&val,    g_val);
    cudaGetSymbolAddress((void**)&off,    g_off);
    cudaGetSymbolAddress((void**)&aw,     g_aw);
    cudaGetSymbolAddress((void**)&attn,   g_attn);
    cudaGetSymbolAddress((void**)&out1,   g_out1);
    cudaGetSymbolAddress((void**)&out2,   g_out2);
    cudaGetSymbolAddress((void**)&tseq,   g_tseq);
    cudaGetSymbolAddress((void**)&ff1,    g_ff1);
    cudaGetSymbolAddress((void**)&out3,   g_out3);

    const dim3 tgrid(IMW / 32, IMH / 16, 1);

    // 1. qk_in
    build_qkin_kernel<<<(BB * HWSZ + 255) / 256, 256>>>(frame, flow_f, flow_b, qkin);

    // 2. qureys = lrelu(conv(qk_in, W_qk))      CIN=100 COUT=96
    conv3x3_kernel<1, 1, false><<<dim3(8, 16, BB * 6), 256>>>(
        qkin, W_qk, b_qk, nullptr, 0, qureys, 100, 96);

    // 3. value = conv(frame(96ch), W_v)         CIN=96 COUT=96
    conv3x3_kernel<1, 0, false><<<dim3(8, 16, BB * 6), 256>>>(
        frame, W_v, b_v, nullptr, 0, value, 96, 96);

    // 4. val = conv(value as 6 x 32ch, W_vp)    nimg=6 CIN=32 COUT=32
    conv3x3_kernel<1, 0, false><<<dim3(8, 16, 6 * 2), 256>>>(
        value, W_vp, b_vp, nullptr, 0, val, 32, 32);

    // 5. off = conv(qureys, W_off)              CIN=96 COUT=96
    conv3x3_kernel<1, 0, false><<<dim3(8, 16, BB * 6), 256>>>(
        qureys, W_off, b_off, nullptr, 0, off, 96, 96);

    // 6. aw = conv(qureys, W_aw)                CIN=96 COUT=48
    conv3x3_kernel<1, 0, false><<<dim3(8, 16, BB * 3), 256>>>(
        qureys, W_aw, b_aw, nullptr, 0, aw, 96, 48);

    // 7. deformable attention
    deform_attn_kernel<<<(BB * 4 * HWSZ + 255) / 256, 256>>>(val, off, aw, attn);

    // 8. out1 = conv(attn, W_out)
    conv3x3_kernel<1, 0, false><<<dim3(8, 16, BB * 2), 256>>>(
        attn, W_out, b_out, nullptr, 0, out1, 32, 32);

    // 9. out2 = conv(out1, W_ffd) + frame[:,1]
    conv3x3_kernel<1, 0, true><<<dim3(8, 16, BB * 2), 256>>>(
        out1, W_ffd, b_ffd, frame + (size_t)32 * HWSZ, (size_t)3 * 32 * HWSZ, out2, 32, 32);

    // 10. tseq = concat(out2, srcframe[:,1])
    build_tseq_kernel<<<(BB * 64 * HWSZ + 255) / 256, 256>>>(out2, srcfr, tseq);

    // 11. ff1 = lrelu(conv(tseq, W_ff1, pad=2, dil=2))   CIN=64 COUT=32
    conv3x3_kernel<2, 1, false><<<dim3(8, 16, BB * 2), 256>>>(
        tseq, W_ff1, b_ff1, nullptr, 0, ff1, 64, 32);

    // 12. out3 = conv(ff1, W_ff2) + out2
    conv3x3_kernel<1, 0, true><<<dim3(8, 16, BB * 2), 256>>>(
        ff1, W_ff2, b_ff2, out2, (size_t)32 * HWSZ, out3, 32, 32);

    // 13. out = lrelu(conv1x1(out3, W_fu))
    conv1x1_lrelu_kernel<<<(BB * HWSZ + 255) / 256, 256>>>(out3, W_fu, b_fu, (float*)d_out);
}

// round 3
// speedup vs baseline: 1.1162x; 1.1162x over previous
#include <cuda_runtime.h>
#include <cstdint>
#include <math.h>

constexpr int IMH = 256, IMW = 256;
constexpr int HWSZ = IMH * IMW;       // 65536
constexpr int BB = 2;

// ---------------- scratch (device globals; no runtime allocation) ----------------
__device__ float g_qkin  [(size_t)BB * 100 * HWSZ];
__device__ float g_qureys[(size_t)BB *  96 * HWSZ];
__device__ float g_value [(size_t)BB *  96 * HWSZ];
__device__ float g_val   [(size_t)BB *  96 * HWSZ];
__device__ float g_off   [(size_t)BB *  96 * HWSZ];
__device__ float g_aw    [(size_t)BB *  48 * HWSZ];
__device__ float g_attn  [(size_t)BB *  32 * HWSZ];
__device__ float g_out1  [(size_t)BB *  32 * HWSZ];
__device__ float g_out2  [(size_t)BB *  32 * HWSZ];
__device__ float g_tseq  [(size_t)BB *  64 * HWSZ];
__device__ float g_ff1   [(size_t)BB *  32 * HWSZ];
__device__ float g_out3  [(size_t)BB *  32 * HWSZ];

__device__ __forceinline__ float lrelu(float v) { return v >= 0.f ? v : 0.1f * v; }

// ---------------- kernel 1: build qk_in (flow warps + concat) ----------------
__device__ __forceinline__ void sample32(const float* __restrict__ img, float sx, float sy,
                                         float* __restrict__ dst, int q)
{
    float x0f = floorf(sx), y0f = floorf(sy);
    float lx = sx - x0f, ly = sy - y0f;
    int x0 = (int)x0f, y0 = (int)y0f;
    float w00 = (1.f - lx) * (1.f - ly);
    float w01 = lx * (1.f - ly);
    float w10 = (1.f - lx) * ly;
    float w11 = lx * ly;
    bool vx0 = (unsigned)x0       < (unsigned)IMW;
    bool vx1 = (unsigned)(x0 + 1) < (unsigned)IMW;
    bool vy0 = (unsigned)y0       < (unsigned)IMH;
    bool vy1 = (unsigned)(y0 + 1) < (unsigned)IMH;
    int cx0 = min(max(x0, 0), IMW - 1), cx1 = min(max(x0 + 1, 0), IMW - 1);
    int cy0 = min(max(y0, 0), IMH - 1), cy1 = min(max(y0 + 1, 0), IMH - 1);
    int i00 = cy0 * IMW + cx0, i01 = cy0 * IMW + cx1;
    int i10 = cy1 * IMW + cx0, i11 = cy1 * IMW + cx1;
    float m00 = (vx0 && vy0) ? w00 : 0.f;
    float m01 = (vx1 && vy0) ? w01 : 0.f;
    float m10 = (vx0 && vy1) ? w10 : 0.f;
    float m11 = (vx1 && vy1) ? w11 : 0.f;
    #pragma unroll 4
    for (int c = 0; c < 32; ++c) {
        const float* p = img + (size_t)c * HWSZ;
        dst[(size_t)c * HWSZ + q] = m00 * p[i00] + m01 * p[i01] + m10 * p[i10] + m11 * p[i11];
    }
}

__global__ void build_qkin_kernel(const float* __restrict__ frame,
                                  const float* __restrict__ flow_f,
                                  const float* __restrict__ flow_b,
                                  float* __restrict__ qkin)
{
    int id = blockIdx.x * blockDim.x + threadIdx.x;
    if (id >= BB * HWSZ) return;
    int b = id / HWSZ, q = id % HWSZ;
    int px = q & (IMW - 1), py = q >> 8;

    const float* fb = flow_b + (size_t)b * 2 * 2 * HWSZ;
    float fbx = fb[q], fby = fb[HWSZ + q];
    const float* ff = flow_f + (size_t)b * 2 * 2 * HWSZ + (size_t)2 * HWSZ;
    float ffx = ff[q], ffy = ff[HWSZ + q];

    float* dst = qkin + (size_t)b * 100 * HWSZ;
    sample32(frame + ((size_t)b * 3 + 0) * 32 * HWSZ, (float)px + fbx, (float)py + fby, dst, q);
    const float* f1 = frame + ((size_t)b * 3 + 1) * 32 * HWSZ;
    #pragma unroll 4
    for (int c = 0; c < 32; ++c)
        dst[(size_t)(32 + c) * HWSZ + q] = f1[(size_t)c * HWSZ + q];
    sample32(frame + ((size_t)b * 3 + 2) * 32 * HWSZ, (float)px + ffx, (float)py + ffy,
             dst + (size_t)64 * HWSZ, q);
    dst[(size_t)96 * HWSZ + q] = ffx;
    dst[(size_t)97 * HWSZ + q] = ffy;
    dst[(size_t)98 * HWSZ + q] = fbx;
    dst[(size_t)99 * HWSZ + q] = fby;
}

// ---------------- cp.async helpers ----------------
__device__ __forceinline__ void cpasync4(unsigned int dst, const float* src, bool ok)
{
    int sz = ok ? 4 : 0;
    asm volatile("cp.async.ca.shared.global [%0], [%1], 4, %2;\n"
                 :: "r"(dst), "l"(src), "r"(sz));
}
__device__ __forceinline__ void cpasync_commit() {
    asm volatile("cp.async.commit_group;\n" ::: "memory");
}
__device__ __forceinline__ void cpasync_wait0() {
    asm volatile("cp.async.wait_group 0;\n" ::: "memory");
}

// ---------------- pipelined tiled 3x3 conv ----------------
// tile: 32(x) x 16(y) output pixels, 16 out channels per block,
// each thread: 2 pixels x 16 oc accumulators. CIN a compile-time multiple of 4.
// Double-buffered cp.async pipeline over 4-channel chunks.
template<int CIN, int DIL, int ACT, bool RES>
__global__ void __launch_bounds__(256, 3) conv3x3_pipe(
    const float* __restrict__ in, const float* __restrict__ Wt,
    const float* __restrict__ bias, const float* __restrict__ res, size_t resStride,
    float* __restrict__ out, int COUT)
{
    constexpr int TX = 32, TY = 16, OCB = 16;
    constexpr int IW = TX + 2 * DIL, IH = TY + 2 * DIL;
    constexpr int NCH = CIN / 4;
    constexpr int TILE_ELEMS = 4 * IH * IW;
    __shared__ float s_in[2][4][IH][IW];
    __shared__ __align__(16) float s_w[2][4][9][OCB];

    const int tid = threadIdx.x;
    const int px = tid & 31, py = tid >> 5;          // px 0..31, py 0..7
    const int x0 = blockIdx.x * TX, y0 = blockIdx.y * TY;
    const int ngrp = COUT >> 4;
    const int img = blockIdx.z / ngrp;
    const int ocBase = (blockIdx.z % ngrp) * OCB;
    const float* inImg = in + (size_t)img * CIN * HWSZ;

    float accA[OCB], accB[OCB];
    #pragma unroll
    for (int i = 0; i < OCB; ++i) { accA[i] = 0.f; accB[i] = 0.f; }

    // ---- prologue: chunk 0 into buffer 0 ----
    {
        #pragma unroll 4
        for (int idx = tid; idx < TILE_ELEMS; idx += 256) {
            int ci = idx / (IH * IW);
            int rem = idx % (IH * IW);
            int ly = rem / IW, lx = rem % IW;
            int gy = y0 - DIL + ly, gx = x0 - DIL + lx;
            bool ok = ((unsigned)gy < (unsigned)IMH) && ((unsigned)gx < (unsigned)IMW);
            int cgy = ok ? gy : 0, cgx = ok ? gx : 0;
            const float* src = inImg + (size_t)ci * HWSZ + cgy * IMW + cgx;
            unsigned int dst = (unsigned int)__cvta_generic_to_shared(&s_in[0][ci][ly][lx]);
            cpasync4(dst, src, ok);
        }
        cpasync_commit();
        #pragma unroll 3
        for (int idx = tid; idx < 4 * 9 * OCB; idx += 256) {
            int oc = idx & 15;
            int k  = (idx >> 4) % 9;
            int ci = (idx >> 4) / 9;
            s_w[0][ci][k][oc] = Wt[((size_t)(ocBase + oc) * CIN + ci) * 9 + k];
        }
        cpasync_wait0();
        __syncthreads();
    }

    int buf = 0;
    #pragma unroll 1
    for (int cc = 0; cc < NCH; ++cc) {
        // ---- prefetch next chunk into buf^1 ----
        if (cc + 1 < NCH) {
            const int nb = buf ^ 1;
            const int ciBase = (cc + 1) * 4;
            #pragma unroll 4
            for (int idx = tid; idx < TILE_ELEMS; idx += 256) {
                int ci = idx / (IH * IW);
                int rem = idx % (IH * IW);
                int ly = rem / IW, lx = rem % IW;
                int gy = y0 - DIL + ly, gx = x0 - DIL + lx;
                bool ok = ((unsigned)gy < (unsigned)IMH) && ((unsigned)gx < (unsigned)IMW);
                int cgy = ok ? gy : 0, cgx = ok ? gx : 0;
                const float* src = inImg + (size_t)(ciBase + ci) * HWSZ + cgy * IMW + cgx;
                unsigned int dst = (unsigned int)__cvta_generic_to_shared(&s_in[nb][ci][ly][lx]);
                cpasync4(dst, src, ok);
            }
            #pragma unroll 3
            for (int idx = tid; idx < 4 * 9 * OCB; idx += 256) {
                int oc = idx & 15;
                int k  = (idx >> 4) % 9;
                int ci = (idx >> 4) / 9;
                s_w[nb][ci][k][oc] = Wt[((size_t)(ocBase + oc) * CIN + ciBase + ci) * 9 + k];
            }
        }
        cpasync_commit();

        // ---- compute current chunk ----
        #pragma unroll
        for (int ci = 0; ci < 4; ++ci) {
            #pragma unroll
            for (int k = 0; k < 9; ++k) {
                const int ky = k / 3, kx = k % 3;
                float xa = s_in[buf][ci][py +     ky * DIL][px + kx * DIL];
                float xb = s_in[buf][ci][py + 8 + ky * DIL][px + kx * DIL];
                const float4* wp = reinterpret_cast<const float4*>(&s_w[buf][ci][k][0]);
                #pragma unroll
                for (int o4 = 0; o4 < 4; ++o4) {
                    float4 w = wp[o4];
                    accA[o4 * 4 + 0] += xa * w.x;  accB[o4 * 4 + 0] += xb * w.x;
                    accA[o4 * 4 + 1] += xa * w.y;  accB[o4 * 4 + 1] += xb * w.y;
                    accA[o4 * 4 + 2] += xa * w.z;  accB[o4 * 4 + 2] += xb * w.z;
                    accA[o4 * 4 + 3] += xa * w.w;  accB[o4 * 4 + 3] += xb * w.w;
                }
            }
        }

        cpasync_wait0();
        __syncthreads();
        buf ^= 1;
    }

    const int ox = x0 + px;
    const int oyA = y0 + py, oyB = y0 + py + 8;
    const size_t outImg = (size_t)img * COUT * HWSZ;
    #pragma unroll
    for (int oc = 0; oc < OCB; ++oc) {
        float bv = bias[ocBase + oc];
        float vA = accA[oc] + bv;
        float vB = accB[oc] + bv;
        if (RES) {
            const float* rp = res + (size_t)img * resStride + (size_t)(ocBase + oc) * HWSZ;
            vA += rp[oyA * IMW + ox];
            vB += rp[oyB * IMW + ox];
        }
        if (ACT) { vA = lrelu(vA); vB = lrelu(vB); }
        size_t chOff = outImg + (size_t)(ocBase + oc) * HWSZ;
        out[chOff + oyA * IMW + ox] = vA;
        out[chOff + oyB * IMW + ox] = vB;
    }
}

// ---------------- deformable attention ----------------
__global__ void deform_attn_kernel(const float* __restrict__ val,
                                   const float* __restrict__ off,
                                   const float* __restrict__ awl,
                                   float* __restrict__ out)
{
    int id = blockIdx.x * blockDim.x + threadIdx.x;
    if (id >= BB * 4 * HWSZ) return;
    int q = id % HWSZ;
    int head = (id / HWSZ) & 3;
    int b = id / (4 * HWSZ);
    int px = q & (IMW - 1), py = q >> 8;

    const float* awp = awl + ((size_t)b * 48 + head * 12) * HWSZ + q;
    float lg[12];
    float mx = -1e30f;
    #pragma unroll
    for (int i = 0; i < 12; ++i) { lg[i] = awp[(size_t)i * HWSZ]; mx = fmaxf(mx, lg[i]); }
    float s = 0.f;
    #pragma unroll
    for (int i = 0; i < 12; ++i) { lg[i] = expf(lg[i] - mx); s += lg[i]; }
    float inv = 1.f / s;

    float acc[8];
    #pragma unroll
    for (int e = 0; e < 8; ++e) acc[e] = 0.f;

    const float* offp = off + ((size_t)b * 96 + head * 24) * HWSZ + q;

    for (int l = 0; l < 3; ++l) {
        const float* vbase = val + (((size_t)b * 3 + l) * 32 + head * 8) * HWSZ;
        #pragma unroll
        for (int p = 0; p < 4; ++p) {
            int ch = (l * 4 + p) * 2;
            float sx = (float)px + offp[(size_t)ch * HWSZ];
            float sy = (float)py + offp[(size_t)(ch + 1) * HWSZ];
            float a = lg[l * 4 + p] * inv;

            float x0f = floorf(sx), y0f = floorf(sy);
            float lx = sx - x0f, ly = sy - y0f;
            int x0 = (int)x0f, y0 = (int)y0f;
            float w00 = (1.f - lx) * (1.f - ly);
            float w01 = lx * (1.f - ly);
            float w10 = (1.f - lx) * ly;
            float w11 = lx * ly;
            bool vx0 = (unsigned)x0       < (unsigned)IMW;
            bool vx1 = (unsigned)(x0 + 1) < (unsigned)IMW;
            bool vy0 = (unsigned)y0       < (unsigned)IMH;
            bool vy1 = (unsigned)(y0 + 1) < (unsigned)IMH;
            int cx0 = min(max(x0, 0), IMW - 1), cx1 = min(max(x0 + 1, 0), IMW - 1);
            int cy0 = min(max(y0, 0), IMH - 1), cy1 = min(max(y0 + 1, 0), IMH - 1);
            float c00 = (vx0 && vy0) ? a * w00 : 0.f;
            float c01 = (vx1 && vy0) ? a * w01 : 0.f;
            float c10 = (vx0 && vy1) ? a * w10 : 0.f;
            float c11 = (vx1 && vy1) ? a * w11 : 0.f;
            int i00 = cy0 * IMW + cx0, i01 = cy0 * IMW + cx1;
            int i10 = cy1 * IMW + cx0, i11 = cy1 * IMW + cx1;
            #pragma unroll
            for (int e = 0; e < 8; ++e) {
                const float* vp = vbase + (size_t)e * HWSZ;
                acc[e] += c00 * vp[i00] + c01 * vp[i01] + c10 * vp[i10] + c11 * vp[i11];
            }
        }
    }

    float* op = out + ((size_t)b * 32 + head * 8) * HWSZ + q;
    #pragma unroll
    for (int e = 0; e < 8; ++e) op[(size_t)e * HWSZ] = acc[e];
}

// ---------------- concat [out2, srcframe[:,1]] ----------------
__global__ void build_tseq_kernel(const float* __restrict__ out2,
                                  const float* __restrict__ srcframe,
                                  float* __restrict__ tseq)
{
    int id = blockIdx.x * blockDim.x + threadIdx.x;
    if (id >= BB * 64 * HWSZ) return;
    int q = id % HWSZ;
    int c = (id / HWSZ) & 63;
    int b = id / (64 * HWSZ);
    float v;
    if (c < 32) v = out2[((size_t)b * 32 + c) * HWSZ + q];
    else        v = srcframe[(((size_t)b * 3 + 1) * 32 + (c - 32)) * HWSZ + q];
    tseq[((size_t)b * 64 + c) * HWSZ + q] = v;
}

// ---------------- final 1x1 conv + lrelu ----------------
__global__ void conv1x1_lrelu_kernel(const float* __restrict__ in,
                                     const float* __restrict__ Wt,
                                     const float* __restrict__ bias,
                                     float* __restrict__ out)
{
    __shared__ float s_w[32][32];
    __shared__ float s_b[32];
    int tid = threadIdx.x;
    for (int idx = tid; idx < 32 * 32; idx += 256)
        s_w[idx >> 5][idx & 31] = Wt[idx];
    if (tid < 32) s_b[tid] = bias[tid];
    __syncthreads();

    int id = blockIdx.x * 256 + tid;
    if (id >= BB * HWSZ) return;
    int b = id / HWSZ, q = id % HWSZ;

    float x[32];
    #pragma unroll
    for (int ci = 0; ci < 32; ++ci)
        x[ci] = in[((size_t)b * 32 + ci) * HWSZ + q];

    #pragma unroll 4
    for (int oc = 0; oc < 32; ++oc) {
        float s = s_b[oc];
        #pragma unroll
        for (int ci = 0; ci < 32; ++ci)
            s += x[ci] * s_w[oc][ci];
        out[((size_t)b * 32 + oc) * HWSZ + q] = lrelu(s);
    }
}

// ---------------- host launcher ----------------
extern "C" void kernel_launch(void* const* d_in, const int* in_sizes, int n_in,
                              void* d_out, int out_size)
{
    const float* frame   = (const float*)d_in[0];
    const float* srcfr   = (const float*)d_in[1];
    const float* flow_f  = (const float*)d_in[2];
    const float* flow_b  = (const float*)d_in[3];
    const float* W_qk = (const float*)d_in[4];   const float* b_qk = (const float*)d_in[5];
    const float* W_v  = (const float*)d_in[6];   const float* b_v  = (const float*)d_in[7];
    const float* W_vp = (const float*)d_in[8];   const float* b_vp = (const float*)d_in[9];
    const float* W_off= (const float*)d_in[10];  const float* b_off= (const float*)d_in[11];
    const float* W_aw = (const float*)d_in[12];  const float* b_aw = (const float*)d_in[13];
    const float* W_out= (const float*)d_in[14];  const float* b_out= (const float*)d_in[15];
    const float* W_ffd= (const float*)d_in[16];  const float* b_ffd= (const float*)d_in[17];
    const float* W_ff1= (const float*)d_in[18];  const float* b_ff1= (const float*)d_in[19];
    const float* W_ff2= (const float*)d_in[20];  const float* b_ff2= (const float*)d_in[21];
    const float* W_fu = (const float*)d_in[22];  const float* b_fu = (const float*)d_in[23];

    float *qkin, *qureys, *value, *val, *off, *aw, *attn, *out1, *out2, *tseq, *ff1, *out3;
    cudaGetSymbolAddress((void**)&qkin,   g_qkin);
    cudaGetSymbolAddress((void**)&qureys, g_qureys);
    cudaGetSymbolAddress((void**)&value,  g_value);
    cudaGetSymbolAddress((void**)&val,    g_val);
    cudaGetSymbolAddress((void**)&off,    g_off);
    cudaGetSymbolAddress((void**)&aw,     g_aw);
    cudaGetSymbolAddress((void**)&attn,   g_attn);
    cudaGetSymbolAddress((void**)&out1,   g_out1);
    cudaGetSymbolAddress((void**)&out2,   g_out2);
    cudaGetSymbolAddress((void**)&tseq,   g_tseq);
    cudaGetSymbolAddress((void**)&ff1,    g_ff1);
    cudaGetSymbolAddress((void**)&out3,   g_out3);

    // 1. qk_in
    build_qkin_kernel<<<(BB * HWSZ + 255) / 256, 256>>>(frame, flow_f, flow_b, qkin);

    // 2. qureys = lrelu(conv(qk_in, W_qk))      CIN=100 COUT=96
    conv3x3_pipe<100, 1, 1, false><<<dim3(8, 16, BB * 6), 256>>>(
        qkin, W_qk, b_qk, nullptr, 0, qureys, 96);

    // 3. value = conv(frame(96ch), W_v)         CIN=96 COUT=96
    conv3x3_pipe<96, 1, 0, false><<<dim3(8, 16, BB * 6), 256>>>(
        frame, W_v, b_v, nullptr, 0, value, 96);

    // 4. val = conv(value as 6 x 32ch, W_vp)    nimg=6 CIN=32 COUT=32
    conv3x3_pipe<32, 1, 0, false><<<dim3(8, 16, 6 * 2), 256>>>(
        value, W_vp, b_vp, nullptr, 0, val, 32);

    // 5. off = conv(qureys, W_off)              CIN=96 COUT=96
    conv3x3_pipe<96, 1, 0, false><<<dim3(8, 16, BB * 6), 256>>>(
        qureys, W_off, b_off, nullptr, 0, off, 96);

    // 6. aw = conv(qureys, W_aw)                CIN=96 COUT=48
    conv3x3_pipe<96, 1, 0, false><<<dim3(8, 16, BB * 3), 256>>>(
        qureys, W_aw, b_aw, nullptr, 0, aw, 48);

    // 7. deformable attention
    deform_attn_kernel<<<(BB * 4 * HWSZ + 255) / 256, 256>>>(val, off, aw, attn);

    // 8. out1 = conv(attn, W_out)
    conv3x3_pipe<32, 1, 0, false><<<dim3(8, 16, BB * 2), 256>>>(
        attn, W_out, b_out, nullptr, 0, out1, 32);

    // 9. out2 = conv(out1, W_ffd) + frame[:,1]
    conv3x3_pipe<32, 1, 0, true><<<dim3(8, 16, BB * 2), 256>>>(
        out1, W_ffd, b_ffd, frame + (size_t)32 * HWSZ, (size_t)3 * 32 * HWSZ, out2, 32);

    // 10. tseq = concat(out2, srcframe[:,1])
    build_tseq_kernel<<<(BB * 64 * HWSZ + 255) / 256, 256>>>(out2, srcfr, tseq);

    // 11. ff1 = lrelu(conv(tseq, W_ff1, pad=2, dil=2))   CIN=64 COUT=32
    conv3x3_pipe<64, 2, 1, false><<<dim3(8, 16, BB * 2), 256>>>(
        tseq, W_ff1, b_ff1, nullptr, 0, ff1, 32);

    // 12. out3 = conv(ff1, W_ff2) + out2
    conv3x3_pipe<32, 1, 0, true><<<dim3(8, 16, BB * 2), 256>>>(
        ff1, W_ff2, b_ff2, out2, (size_t)32 * HWSZ, out3, 32);

    // 13. out = lrelu(conv1x1(out3, W_fu))
    conv1x1_lrelu_kernel<<<(BB * HWSZ + 255) / 256, 256>>>(out3, W_fu, b_fu, (float*)d_out);
}